// round 13
// baseline (speedup 1.0000x reference)
#include <cuda_runtime.h>
#include <cuda_bf16.h>
#include <math.h>
#include <stdint.h>

// Problem constants
#define D_   2048
#define S_   2048
#define B_   2
#define H_   16
#define DK_  128
#define BS_  (B_*S_)   // 4096 tokens
#define BH_  (B_*H_)   // 32 head-batches

// ---------------------------------------------------------------------------
// Helpers
// ---------------------------------------------------------------------------
__device__ __forceinline__ uint32_t smem_u32(const void* p) {
    uint32_t a;
    asm("{ .reg .u64 t; cvta.to.shared.u64 t, %1; cvt.u32.u64 %0, t; }"
        : "=r"(a) : "l"(p));
    return a;
}
#define CP16(dst, src) \
    asm volatile("cp.async.cg.shared.global [%0], [%1], 16;" :: "r"(dst), "l"(src))
#define CP_COMMIT() asm volatile("cp.async.commit_group;" ::: "memory")
#define CP_WAIT(n)  asm volatile("cp.async.wait_group %0;" :: "n"(n) : "memory")

__device__ __forceinline__ void ldsm4(uint32_t* r, uint32_t addr) {
    asm volatile("ldmatrix.sync.aligned.m8n8.x4.shared.b16 {%0,%1,%2,%3}, [%4];"
        : "=r"(r[0]), "=r"(r[1]), "=r"(r[2]), "=r"(r[3]) : "r"(addr));
}
__device__ __forceinline__ void ldsm4t(uint32_t* r, uint32_t addr) {
    asm volatile("ldmatrix.sync.aligned.m8n8.x4.trans.shared.b16 {%0,%1,%2,%3}, [%4];"
        : "=r"(r[0]), "=r"(r[1]), "=r"(r[2]), "=r"(r[3]) : "r"(addr));
}
__device__ __forceinline__ void mma_bf16(float* d, const uint32_t* a, const uint32_t* b) {
    asm volatile("mma.sync.aligned.m16n8k16.row.col.f32.bf16.bf16.f32 "
        "{%0,%1,%2,%3}, {%4,%5,%6,%7}, {%8,%9}, {%0,%1,%2,%3};"
        : "+f"(d[0]), "+f"(d[1]), "+f"(d[2]), "+f"(d[3])
        : "r"(a[0]), "r"(a[1]), "r"(a[2]), "r"(a[3]), "r"(b[0]), "r"(b[1]));
}

// ---------------------------------------------------------------------------
// Device scratch (no allocations allowed)
// ---------------------------------------------------------------------------
__device__ __nv_bfloat16 g_ah[BS_*D_],  g_al[BS_*D_];    // flash out -> O proj
__device__ __nv_bfloat16 g_ahq[BS_*D_], g_alq[BS_*D_];
__device__ __nv_bfloat16 g_ahk[BS_*D_], g_alk[BS_*D_];
__device__ __nv_bfloat16 g_ahv[BS_*D_], g_alv[BS_*D_];
__device__ __nv_bfloat16 g_whq[D_*D_], g_wlq[D_*D_];
__device__ __nv_bfloat16 g_whk[D_*D_], g_wlk[D_*D_];
__device__ __nv_bfloat16 g_whv[D_*D_], g_wlv[D_*D_];
__device__ __nv_bfloat16 g_who[D_*D_], g_wlo[D_*D_];
__device__ __nv_bfloat16 g_qh[BH_*S_*DK_], g_ql[BH_*S_*DK_];
__device__ __nv_bfloat16 g_kh[BH_*S_*DK_], g_kl[BH_*S_*DK_];
__device__ __nv_bfloat16 g_vh[BH_*S_*DK_], g_vl[BH_*S_*DK_];

// Batch parameter structs (passed by value)
struct PrepBatch {
    // z = 0..3: weight LoRA+transpose+split
    const float* w[4]; const float* la[4]; const float* lb[4];
    __nv_bfloat16* whi[4]; __nv_bfloat16* wlo[4];
    // z = 4..6: activation split
    const float* x[3];
    __nv_bfloat16* hi[3]; __nv_bfloat16* lo[3];
};
struct GemmBatch {
    const __nv_bfloat16* ah[3]; const __nv_bfloat16* al[3];
    const __nv_bfloat16* wh[3]; const __nv_bfloat16* wl[3];
    const float* bias[3];
    float scale[3];
    float* c[3];
    __nv_bfloat16* chi[3]; __nv_bfloat16* clo[3];
};

// ---------------------------------------------------------------------------
// Combined prep: weight splits (z<4) + activation splits (z>=4), one launch.
// Grid (64, 64, 7), 256 threads.
// ---------------------------------------------------------------------------
__global__ void prep_kernel(PrepBatch pb)
{
    __shared__ float t[32][33];
    const int z = blockIdx.z;
    if (z < 4) {
        const float* __restrict__ w  = pb.w[z];
        const float* __restrict__ la = pb.la[z];
        const float* __restrict__ lb = pb.lb[z];
        __nv_bfloat16* __restrict__ whi = pb.whi[z];
        __nv_bfloat16* __restrict__ wlo = pb.wlo[z];

        const int k0 = blockIdx.y * 32, n0 = blockIdx.x * 32;
        const int x = threadIdx.x & 31, y = threadIdx.x >> 5;
#pragma unroll
        for (int i = 0; i < 4; i++) {
            int k = k0 + y + 8 * i;
            float v = w[k * D_ + n0 + x];
#pragma unroll
            for (int r = 0; r < 8; r++)
                v += la[k * 8 + r] * lb[r * D_ + n0 + x];
            t[y + 8 * i][x] = v;
        }
        __syncthreads();
#pragma unroll
        for (int i = 0; i < 4; i++) {
            int nl = y + 8 * i;
            float v = t[x][nl];
            __nv_bfloat16 h = __float2bfloat16(v);
            whi[(n0 + nl) * D_ + k0 + x] = h;
            wlo[(n0 + nl) * D_ + k0 + x] = __float2bfloat16(v - __bfloat162float(h));
        }
    } else {
        const int a = z - 4;
        const float* __restrict__ x = pb.x[a];
        __nv_bfloat16* __restrict__ hi = pb.hi[a];
        __nv_bfloat16* __restrict__ lo = pb.lo[a];

        // linear block over (64,64): 2048 floats per block, 8 per thread
        const int blk = blockIdx.y * 64 + blockIdx.x;
        int i = blk * 2048 + threadIdx.x * 8;
#pragma unroll
        for (int u = 0; u < 2; u++, i += 4) {
            float4 v = *(const float4*)(x + i);
            __nv_bfloat16 h0 = __float2bfloat16(v.x);
            __nv_bfloat16 h1 = __float2bfloat16(v.y);
            __nv_bfloat16 h2 = __float2bfloat16(v.z);
            __nv_bfloat16 h3 = __float2bfloat16(v.w);
            *(__nv_bfloat162*)(hi + i)     = __nv_bfloat162(h0, h1);
            *(__nv_bfloat162*)(hi + i + 2) = __nv_bfloat162(h2, h3);
            *(__nv_bfloat162*)(lo + i) = __nv_bfloat162(
                __float2bfloat16(v.x - __bfloat162float(h0)),
                __float2bfloat16(v.y - __bfloat162float(h1)));
            *(__nv_bfloat162*)(lo + i + 2) = __nv_bfloat162(
                __float2bfloat16(v.z - __bfloat162float(h2)),
                __float2bfloat16(v.w - __bfloat162float(h3)));
        }
    }
}

// ---------------------------------------------------------------------------
// bf16x3 GEMM via mma.sync (CTA 128x128, K-chunk 32). blockIdx.z selects the
// batch entry. epi==1: bf16 hi/lo head-major scaled by gb.scale[z];
// epi==0: fp32 row-major.
// Occupancy is steered PER LAUNCH via the dynamic smem size: 80 KB -> 2
// CTAs/SM (O proj, 512 CTAs = 1.73 waves of 296); 118 KB -> 1 CTA/SM (QKV,
// 1536 CTAs = 10.4 waves of 148, tail idle 15.6% -> 6%).
// ---------------------------------------------------------------------------
#define RSTRIDE 80                        // 64 B data + 16 B pad
#define GT      (128 * RSTRIDE)           // 10240
#define GBUF    (4 * GT)                  // 40960
#define GSMEM   (2 * GBUF)                // 81920 (2 CTAs/SM)
#define GSMEM1  120832                    // > 227KB/2 -> forces 1 CTA/SM

__global__ __launch_bounds__(256, 2) void gemm_bf16x3(GemmBatch gb, int epi)
{
    extern __shared__ char dsm[];
    const uint32_t sb = smem_u32(dsm);

    const int z    = blockIdx.z;
    const int tid  = threadIdx.x;
    const int wid  = tid >> 5;
    const int lane = tid & 31;
    const int wm   = wid >> 1;
    const int wn   = wid & 1;
    const int bm   = blockIdx.y << 7;
    const int bn   = blockIdx.x << 7;

    const __nv_bfloat16* srcs[4] = {
        gb.ah[z] + (size_t)bm * D_, gb.al[z] + (size_t)bm * D_,
        gb.wh[z] + (size_t)bn * D_, gb.wl[z] + (size_t)bn * D_ };
    const float* __restrict__ bias = gb.bias[z];

    float acc[2][8][4];
#pragma unroll
    for (int i = 0; i < 2; i++)
#pragma unroll
        for (int j = 0; j < 8; j++)
#pragma unroll
            for (int q = 0; q < 4; q++) acc[i][j][q] = 0.f;

    const int a_row  = lane & 15;
    const int a_half = lane >> 4;
    const int b_row  = (lane & 7) + ((lane & 16) ? 8 : 0);
    const int b_kh   = (lane >> 3) & 1;

    auto issue_tile = [&](int c, int buf) {
        const uint32_t bb = sb + buf * GBUF;
        const int ke = c * 32;
#pragma unroll
        for (int t = 0; t < 4; t++) {
            const __nv_bfloat16* src = srcs[t] + ke;
            const uint32_t db = bb + t * GT;
#pragma unroll
            for (int j = 0; j < 2; j++) {
                int idx = j * 256 + tid;
                int row = idx >> 2, c16 = idx & 3;
                CP16(db + row * RSTRIDE + c16 * 16,
                     src + (size_t)row * D_ + c16 * 8);
            }
        }
        CP_COMMIT();
    };

    issue_tile(0, 0);

#pragma unroll 1
    for (int c = 0; c < 64; c++) {
        const int buf = c & 1;
        if (c < 63) issue_tile(c + 1, buf ^ 1);
        if (c < 63) { CP_WAIT(1); } else { CP_WAIT(0); }
        __syncthreads();

        const uint32_t bb = sb + buf * GBUF;
        const uint32_t aBase = bb + (wm * 32 + a_row) * RSTRIDE + a_half * 16;
        const uint32_t bBase = bb + 2 * GT + (wn * 64 + b_row) * RSTRIDE + b_kh * 16;

#pragma unroll
        for (int ks = 0; ks < 2; ks++) {
            const uint32_t ko = ks * 32;
            uint32_t ah2[2][4], al2[2][4];
#pragma unroll
            for (int mf = 0; mf < 2; mf++) {
                ldsm4(ah2[mf], aBase + mf * 16 * RSTRIDE + ko);
                ldsm4(al2[mf], aBase + GT + mf * 16 * RSTRIDE + ko);
            }
            uint32_t bh2[4][4], bl2[4][4];
#pragma unroll
            for (int ng = 0; ng < 4; ng++) {
                ldsm4(bh2[ng], bBase + ng * 16 * RSTRIDE + ko);
                ldsm4(bl2[ng], bBase + GT + ng * 16 * RSTRIDE + ko);
            }
#pragma unroll
            for (int mf = 0; mf < 2; mf++) {
#pragma unroll
                for (int ng = 0; ng < 4; ng++) {
                    mma_bf16(acc[mf][2 * ng],     ah2[mf], &bh2[ng][0]);
                    mma_bf16(acc[mf][2 * ng + 1], ah2[mf], &bh2[ng][2]);
                    mma_bf16(acc[mf][2 * ng],     ah2[mf], &bl2[ng][0]);
                    mma_bf16(acc[mf][2 * ng + 1], ah2[mf], &bl2[ng][2]);
                    mma_bf16(acc[mf][2 * ng],     al2[mf], &bh2[ng][0]);
                    mma_bf16(acc[mf][2 * ng + 1], al2[mf], &bh2[ng][2]);
                }
            }
        }
        __syncthreads();
    }

    const int h = blockIdx.x;             // N-tile == one head when epi==1
    const float osc = gb.scale[z];
#pragma unroll
    for (int mf = 0; mf < 2; mf++) {
        const int r0 = bm + wm * 32 + mf * 16 + (lane >> 2);
#pragma unroll
        for (int rr = 0; rr < 2; rr++) {
            const int g = r0 + rr * 8;
            if (epi == 1) {
                int b = g >> 11, s = g & (S_ - 1);
                size_t base = ((size_t)((b * H_ + h) * S_ + s)) * DK_;
                __nv_bfloat16* Chi = gb.chi[z];
                __nv_bfloat16* Clo = gb.clo[z];
#pragma unroll
                for (int nf = 0; nf < 8; nf++) {
                    const int col = wn * 64 + nf * 8 + 2 * (lane & 3);
                    float vx = (acc[mf][nf][2 * rr + 0] + bias[bn + col]) * osc;
                    float vy = (acc[mf][nf][2 * rr + 1] + bias[bn + col + 1]) * osc;
                    __nv_bfloat16 hx = __float2bfloat16(vx);
                    __nv_bfloat16 hy = __float2bfloat16(vy);
                    *(__nv_bfloat162*)(Chi + base + col) = __nv_bfloat162(hx, hy);
                    *(__nv_bfloat162*)(Clo + base + col) = __nv_bfloat162(
                        __float2bfloat16(vx - __bfloat162float(hx)),
                        __float2bfloat16(vy - __bfloat162float(hy)));
                }
            } else {
                float* dst = gb.c[z] + (size_t)g * D_ + bn;
#pragma unroll
                for (int nf = 0; nf < 8; nf++) {
                    const int col = wn * 64 + nf * 8 + 2 * (lane & 3);
                    float2 v;
                    v.x = acc[mf][nf][2 * rr + 0] + bias[bn + col];
                    v.y = acc[mf][nf][2 * rr + 1] + bias[bn + col + 1];
                    *(float2*)(dst + col) = v;
                }
            }
        }
    }
}

// ---------------------------------------------------------------------------
// Tensor-core causal flash attention, bf16x3 splits, fp32 softmax.
// R10 geometry: BM=128 (8 warps x 16 rows), BN=64, dk=128, FR=272.
// Q is pre-scaled by 1/sqrt(dk) in the projection epilogue.
// ---------------------------------------------------------------------------
#define FR       272
#define FQT      (128 * FR)               // 34816
#define FKT      (64 * FR)                // 17408
#define FST      (4 * FKT)                // 69632
#define FST_OFF  (2 * FQT)
#define FSMEM    (2 * FQT + 2 * FST)      // 208896

__global__ __launch_bounds__(256, 1) void flash_tc(
    const __nv_bfloat16* __restrict__ Qh, const __nv_bfloat16* __restrict__ Ql,
    const __nv_bfloat16* __restrict__ Kh, const __nv_bfloat16* __restrict__ Kl,
    const __nv_bfloat16* __restrict__ Vh, const __nv_bfloat16* __restrict__ Vl,
    __nv_bfloat16* __restrict__ Oh, __nv_bfloat16* __restrict__ Ol)
{
    extern __shared__ char dsm[];
    const uint32_t sb = smem_u32(dsm);

    const int tid  = threadIdx.x;
    const int w    = tid >> 5;
    const int lane = tid & 31;
    const int qb   = 15 - blockIdx.x;     // heavy blocks first
    const int bh   = blockIdx.y;
    const int qm0  = qb * 128;

    {
        const __nv_bfloat16* qsrc[2] = {
            Qh + ((size_t)bh * S_ + qm0) * DK_,
            Ql + ((size_t)bh * S_ + qm0) * DK_ };
#pragma unroll
        for (int t = 0; t < 2; t++)
#pragma unroll
            for (int j = 0; j < 8; j++) {
                int idx = j * 256 + tid;
                int row = idx >> 4, c16 = idx & 15;
                CP16(sb + t * FQT + row * FR + c16 * 16,
                     qsrc[t] + (size_t)row * DK_ + c16 * 8);
            }
        CP_COMMIT();
    }
    const __nv_bfloat16* ksrc[4] = {
        Kh + (size_t)bh * S_ * DK_, Kl + (size_t)bh * S_ * DK_,
        Vh + (size_t)bh * S_ * DK_, Vl + (size_t)bh * S_ * DK_ };

    auto issue_kv = [&](int kn, int buf) {
        const uint32_t bb = sb + FST_OFF + buf * FST;
        const int ke = kn * 64;
#pragma unroll
        for (int t = 0; t < 4; t++) {
            const __nv_bfloat16* src = ksrc[t] + (size_t)ke * DK_;
            const uint32_t db = bb + t * FKT;
#pragma unroll
            for (int j = 0; j < 4; j++) {
                int idx = j * 256 + tid;
                int row = idx >> 4, c16 = idx & 15;
                CP16(db + row * FR + c16 * 16,
                     src + (size_t)row * DK_ + c16 * 8);
            }
        }
        CP_COMMIT();
    };
    issue_kv(0, 0);

    float oacc[16][4];
#pragma unroll
    for (int i = 0; i < 16; i++)
#pragma unroll
        for (int q = 0; q < 4; q++) oacc[i][q] = 0.f;
    float m_i[2] = {-1e30f, -1e30f};
    float l_i[2] = {0.f, 0.f};

    const int ntiles = 2 * qb + 2;
    const int grp = lane >> 2, tig = lane & 3;

    const int a_row  = lane & 15, a_half = lane >> 4;
    const int b_row  = (lane & 7) + ((lane & 16) ? 8 : 0);
    const int b_kh   = (lane >> 3) & 1;
    const int vt_row = (lane & 7) + 8 * ((lane >> 3) & 1);
    const int vt_nb  = 16 * (lane >> 4);

#pragma unroll 1
    for (int kn = 0; kn < ntiles; kn++) {
        const int buf = kn & 1;
        if (kn + 1 < ntiles) issue_kv(kn + 1, buf ^ 1);
        if (kn + 1 < ntiles) { CP_WAIT(1); } else { CP_WAIT(0); }
        __syncthreads();

        const uint32_t st = sb + FST_OFF + buf * FST;

        // ---- S = Qh·Kh + Qh·Kl + Ql·Kh  (128x64, fp32 acc) ----
        float sacc[8][4];
#pragma unroll
        for (int i = 0; i < 8; i++)
#pragma unroll
            for (int q = 0; q < 4; q++) sacc[i][q] = 0.f;

        const uint32_t qBase = sb + (16 * w + a_row) * FR + a_half * 16;
        const uint32_t kBase = st + b_row * FR + b_kh * 16;

#pragma unroll
        for (int ks = 0; ks < 8; ks++) {
            const uint32_t ko = ks * 32;
            uint32_t qhf[4], qlf[4];
            ldsm4(qhf, qBase + ko);
            ldsm4(qlf, qBase + FQT + ko);
            uint32_t kh2[4][4], kl2[4][4];
#pragma unroll
            for (int ng = 0; ng < 4; ng++) {
                ldsm4(kh2[ng], kBase + ng * 16 * FR + ko);
                ldsm4(kl2[ng], kBase + FKT + ng * 16 * FR + ko);
            }
#pragma unroll
            for (int ng = 0; ng < 4; ng++) {
                mma_bf16(sacc[2 * ng],     qhf, &kh2[ng][0]);
                mma_bf16(sacc[2 * ng + 1], qhf, &kh2[ng][2]);
                mma_bf16(sacc[2 * ng],     qhf, &kl2[ng][0]);
                mma_bf16(sacc[2 * ng + 1], qhf, &kl2[ng][2]);
                mma_bf16(sacc[2 * ng],     qlf, &kh2[ng][0]);
                mma_bf16(sacc[2 * ng + 1], qlf, &kh2[ng][2]);
            }
        }

        // ---- causal mask (scale pre-folded into Q) ----
        const bool boundary = (kn >= 2 * qb);
        if (boundary) {
            const int r0 = qm0 + 16 * w + grp;
            const int r1 = r0 + 8;
#pragma unroll
            for (int nf = 0; nf < 8; nf++) {
                const int c0 = kn * 64 + nf * 8 + 2 * tig;
                if (c0     > r0) sacc[nf][0] = -1e30f;
                if (c0 + 1 > r0) sacc[nf][1] = -1e30f;
                if (c0     > r1) sacc[nf][2] = -1e30f;
                if (c0 + 1 > r1) sacc[nf][3] = -1e30f;
            }
        }

        // ---- online softmax (per row-half; stats across 4 lanes) ----
#pragma unroll
        for (int hh = 0; hh < 2; hh++) {
            float mx = -1e30f;
#pragma unroll
            for (int nf = 0; nf < 8; nf++)
                mx = fmaxf(mx, fmaxf(sacc[nf][2 * hh], sacc[nf][2 * hh + 1]));
            mx = fmaxf(mx, __shfl_xor_sync(0xffffffffu, mx, 1));
            mx = fmaxf(mx, __shfl_xor_sync(0xffffffffu, mx, 2));
            float mn = fmaxf(m_i[hh], mx);
            float alpha = __expf(m_i[hh] - mn);
            float rs = 0.f;
#pragma unroll
            for (int nf = 0; nf < 8; nf++) {
                float p0 = __expf(sacc[nf][2 * hh]     - mn);
                float p1 = __expf(sacc[nf][2 * hh + 1] - mn);
                sacc[nf][2 * hh] = p0; sacc[nf][2 * hh + 1] = p1;
                rs += p0 + p1;
            }
            rs += __shfl_xor_sync(0xffffffffu, rs, 1);
            rs += __shfl_xor_sync(0xffffffffu, rs, 2);
            l_i[hh] = l_i[hh] * alpha + rs;
            m_i[hh] = mn;
#pragma unroll
            for (int nf = 0; nf < 16; nf++) {
                oacc[nf][2 * hh] *= alpha; oacc[nf][2 * hh + 1] *= alpha;
            }
        }

        // ---- pack P (C-layout -> A-frag), split hi/lo ----
        uint32_t ph[4][4], pl[4][4];
#pragma unroll
        for (int j = 0; j < 4; j++) {
#pragma unroll
            for (int q = 0; q < 4; q++) {
                float x0 = sacc[2 * j + (q >> 1)][(q & 1) ? 2 : 0];
                float x1 = sacc[2 * j + (q >> 1)][(q & 1) ? 3 : 1];
                __nv_bfloat16 h0 = __float2bfloat16(x0);
                __nv_bfloat16 h1 = __float2bfloat16(x1);
                __nv_bfloat162 hp = __nv_bfloat162(h0, h1);
                ph[j][q] = *(uint32_t*)&hp;
                __nv_bfloat162 lp = __nv_bfloat162(
                    __float2bfloat16(x0 - __bfloat162float(h0)),
                    __float2bfloat16(x1 - __bfloat162float(h1)));
                pl[j][q] = *(uint32_t*)&lp;
            }
        }

        // ---- O += Ph·Vh + Ph·Vl + Pl·Vh  (V via ldmatrix.trans) ----
        const uint32_t vBase = st + 2 * FKT + vt_row * FR + vt_nb;
#pragma unroll
        for (int ks = 0; ks < 4; ks++) {
            const uint32_t kro = ks * 16 * FR;
            uint32_t vh2[8][4], vl2[8][4];
#pragma unroll
            for (int vg = 0; vg < 8; vg++) {
                ldsm4t(vh2[vg], vBase + kro + vg * 32);
                ldsm4t(vl2[vg], vBase + FKT + kro + vg * 32);
            }
#pragma unroll
            for (int vg = 0; vg < 8; vg++) {
                mma_bf16(oacc[2 * vg],     ph[ks], &vh2[vg][0]);
                mma_bf16(oacc[2 * vg + 1], ph[ks], &vh2[vg][2]);
                mma_bf16(oacc[2 * vg],     ph[ks], &vl2[vg][0]);
                mma_bf16(oacc[2 * vg + 1], ph[ks], &vl2[vg][2]);
                mma_bf16(oacc[2 * vg],     pl[ks], &vh2[vg][0]);
                mma_bf16(oacc[2 * vg + 1], pl[ks], &vh2[vg][2]);
            }
        }
        __syncthreads();
    }

    // ---- epilogue: normalize, split hi/lo, store token-major [B,S,D] ----
    const int b = bh >> 4, h = bh & 15;
    const float inv0 = 1.f / l_i[0], inv1 = 1.f / l_i[1];
    const int row0 = qm0 + 16 * w + grp;
    const size_t t0 = ((size_t)b * S_ + row0) * D_;
    const size_t t1 = t0 + 8 * D_;
#pragma unroll
    for (int nf = 0; nf < 16; nf++) {
        const int col = h * DK_ + nf * 8 + 2 * tig;
        float v0 = oacc[nf][0] * inv0, v1 = oacc[nf][1] * inv0;
        float v2 = oacc[nf][2] * inv1, v3 = oacc[nf][3] * inv1;
        __nv_bfloat16 h0 = __float2bfloat16(v0), h1 = __float2bfloat16(v1);
        __nv_bfloat16 h2 = __float2bfloat16(v2), h3 = __float2bfloat16(v3);
        *(__nv_bfloat162*)(Oh + t0 + col) = __nv_bfloat162(h0, h1);
        *(__nv_bfloat162*)(Oh + t1 + col) = __nv_bfloat162(h2, h3);
        *(__nv_bfloat162*)(Ol + t0 + col) = __nv_bfloat162(
            __float2bfloat16(v0 - __bfloat162float(h0)),
            __float2bfloat16(v1 - __bfloat162float(h1)));
        *(__nv_bfloat162*)(Ol + t1 + col) = __nv_bfloat162(
            __float2bfloat16(v2 - __bfloat162float(h2)),
            __float2bfloat16(v3 - __bfloat162float(h3)));
    }
}

// ---------------------------------------------------------------------------
// Launcher: 4 launches total.
// ---------------------------------------------------------------------------
extern "C" void kernel_launch(void* const* d_in, const int* in_sizes, int n_in,
                              void* d_out, int out_size)
{
    const float* query = (const float*)d_in[0];
    const float* key   = (const float*)d_in[1];
    const float* value = (const float*)d_in[2];
    const float* wq  = (const float*)d_in[3];
    const float* bq  = (const float*)d_in[4];
    const float* laq = (const float*)d_in[5];
    const float* lbq = (const float*)d_in[6];
    const float* wk  = (const float*)d_in[7];
    const float* bk  = (const float*)d_in[8];
    const float* lak = (const float*)d_in[9];
    const float* lbk = (const float*)d_in[10];
    const float* wv  = (const float*)d_in[11];
    const float* bv  = (const float*)d_in[12];
    const float* lav = (const float*)d_in[13];
    const float* lbv = (const float*)d_in[14];
    const float* wo  = (const float*)d_in[15];
    const float* bo  = (const float*)d_in[16];
    const float* lao = (const float*)d_in[17];
    const float* lbo = (const float*)d_in[18];

    __nv_bfloat16 *ah, *al, *ahq, *alq, *ahk, *alk, *ahv, *alv;
    __nv_bfloat16 *whq, *wlq, *whk, *wlk, *whv, *wlv, *who, *wlo_;
    __nv_bfloat16 *qh, *ql, *kh, *kl, *vh, *vl;
    cudaGetSymbolAddress((void**)&ah,  g_ah);
    cudaGetSymbolAddress((void**)&al,  g_al);
    cudaGetSymbolAddress((void**)&ahq, g_ahq);
    cudaGetSymbolAddress((void**)&alq, g_alq);
    cudaGetSymbolAddress((void**)&ahk, g_ahk);
    cudaGetSymbolAddress((void**)&alk, g_alk);
    cudaGetSymbolAddress((void**)&ahv, g_ahv);
    cudaGetSymbolAddress((void**)&alv, g_alv);
    cudaGetSymbolAddress((void**)&whq, g_whq);
    cudaGetSymbolAddress((void**)&wlq, g_wlq);
    cudaGetSymbolAddress((void**)&whk, g_whk);
    cudaGetSymbolAddress((void**)&wlk, g_wlk);
    cudaGetSymbolAddress((void**)&whv, g_whv);
    cudaGetSymbolAddress((void**)&wlv, g_wlv);
    cudaGetSymbolAddress((void**)&who, g_who);
    cudaGetSymbolAddress((void**)&wlo_, g_wlo);
    cudaGetSymbolAddress((void**)&qh, g_qh);
    cudaGetSymbolAddress((void**)&ql, g_ql);
    cudaGetSymbolAddress((void**)&kh, g_kh);
    cudaGetSymbolAddress((void**)&kl, g_kl);
    cudaGetSymbolAddress((void**)&vh, g_vh);
    cudaGetSymbolAddress((void**)&vl, g_vl);

    cudaFuncSetAttribute((const void*)gemm_bf16x3,
                         cudaFuncAttributeMaxDynamicSharedMemorySize, GSMEM1);
    cudaFuncSetAttribute((const void*)flash_tc,
                         cudaFuncAttributeMaxDynamicSharedMemorySize, FSMEM);

    // 1) All weight + activation splits in ONE launch
    PrepBatch pb;
    pb.w[0] = wq; pb.la[0] = laq; pb.lb[0] = lbq; pb.whi[0] = whq; pb.wlo[0] = wlq;
    pb.w[1] = wk; pb.la[1] = lak; pb.lb[1] = lbk; pb.whi[1] = whk; pb.wlo[1] = wlk;
    pb.w[2] = wv; pb.la[2] = lav; pb.lb[2] = lbv; pb.whi[2] = whv; pb.wlo[2] = wlv;
    pb.w[3] = wo; pb.la[3] = lao; pb.lb[3] = lbo; pb.whi[3] = who; pb.wlo[3] = wlo_;
    pb.x[0] = query; pb.hi[0] = ahq; pb.lo[0] = alq;
    pb.x[1] = key;   pb.hi[1] = ahk; pb.lo[1] = alk;
    pb.x[2] = value; pb.hi[2] = ahv; pb.lo[2] = alv;
    prep_kernel<<<dim3(64, 64, 7), 256>>>(pb);

    // 2) Q,K,V projections in ONE launch (Q pre-scaled by 1/sqrt(dk)).
    //    Dynamic smem = GSMEM1 forces 1 CTA/SM: 1536 CTAs / 148 = 10.4 waves
    //    (tail idle 6%) instead of 1536 / 296 = 5.19 waves (tail idle 15.6%).
    const float qscale = 0.08838834764831845f;
    GemmBatch gqkv = {};
    gqkv.ah[0] = ahq; gqkv.al[0] = alq; gqkv.wh[0] = whq; gqkv.wl[0] = wlq;
    gqkv.bias[0] = bq; gqkv.scale[0] = qscale; gqkv.chi[0] = qh; gqkv.clo[0] = ql;
    gqkv.ah[1] = ahk; gqkv.al[1] = alk; gqkv.wh[1] = whk; gqkv.wl[1] = wlk;
    gqkv.bias[1] = bk; gqkv.scale[1] = 1.f; gqkv.chi[1] = kh; gqkv.clo[1] = kl;
    gqkv.ah[2] = ahv; gqkv.al[2] = alv; gqkv.wh[2] = whv; gqkv.wl[2] = wlv;
    gqkv.bias[2] = bv; gqkv.scale[2] = 1.f; gqkv.chi[2] = vh; gqkv.clo[2] = vl;
    gemm_bf16x3<<<dim3(D_ / 128, BS_ / 128, 3), 256, GSMEM1>>>(gqkv, 1);

    // 3) Tensor-core causal flash attention (R10 geometry)
    flash_tc<<<dim3(16, BH_), 256, FSMEM>>>(qh, ql, kh, kl, vh, vl, ah, al);

    // 4) Output projection -> d_out (fp32); 2 CTAs/SM (better at 512 CTAs)
    GemmBatch go = {};
    go.ah[0] = ah; go.al[0] = al; go.wh[0] = who; go.wl[0] = wlo_;
    go.bias[0] = bo; go.scale[0] = 1.f; go.c[0] = (float*)d_out;
    gemm_bf16x3<<<dim3(D_ / 128, BS_ / 128, 1), 256, GSMEM>>>(go, 0);
}

// round 15
// speedup vs baseline: 1.1336x; 1.1336x over previous
#include <cuda_runtime.h>
#include <cuda_bf16.h>
#include <math.h>
#include <stdint.h>

// Problem constants
#define D_   2048
#define S_   2048
#define B_   2
#define H_   16
#define DK_  128
#define BS_  (B_*S_)   // 4096 tokens
#define BH_  (B_*H_)   // 32 head-batches

// ---------------------------------------------------------------------------
// Helpers
// ---------------------------------------------------------------------------
__device__ __forceinline__ uint32_t smem_u32(const void* p) {
    uint32_t a;
    asm("{ .reg .u64 t; cvta.to.shared.u64 t, %1; cvt.u32.u64 %0, t; }"
        : "=r"(a) : "l"(p));
    return a;
}
#define CP16(dst, src) \
    asm volatile("cp.async.cg.shared.global [%0], [%1], 16;" :: "r"(dst), "l"(src))
#define CP_COMMIT() asm volatile("cp.async.commit_group;" ::: "memory")
#define CP_WAIT(n)  asm volatile("cp.async.wait_group %0;" :: "n"(n) : "memory")

__device__ __forceinline__ void ldsm4(uint32_t* r, uint32_t addr) {
    asm volatile("ldmatrix.sync.aligned.m8n8.x4.shared.b16 {%0,%1,%2,%3}, [%4];"
        : "=r"(r[0]), "=r"(r[1]), "=r"(r[2]), "=r"(r[3]) : "r"(addr));
}
__device__ __forceinline__ void ldsm4t(uint32_t* r, uint32_t addr) {
    asm volatile("ldmatrix.sync.aligned.m8n8.x4.trans.shared.b16 {%0,%1,%2,%3}, [%4];"
        : "=r"(r[0]), "=r"(r[1]), "=r"(r[2]), "=r"(r[3]) : "r"(addr));
}
__device__ __forceinline__ void mma_bf16(float* d, const uint32_t* a, const uint32_t* b) {
    asm volatile("mma.sync.aligned.m16n8k16.row.col.f32.bf16.bf16.f32 "
        "{%0,%1,%2,%3}, {%4,%5,%6,%7}, {%8,%9}, {%0,%1,%2,%3};"
        : "+f"(d[0]), "+f"(d[1]), "+f"(d[2]), "+f"(d[3])
        : "r"(a[0]), "r"(a[1]), "r"(a[2]), "r"(a[3]), "r"(b[0]), "r"(b[1]));
}

// ---------------------------------------------------------------------------
// Device scratch (no allocations allowed)
// ---------------------------------------------------------------------------
__device__ __nv_bfloat16 g_ah[BS_*D_],  g_al[BS_*D_];    // flash out -> O proj
__device__ __nv_bfloat16 g_ahq[BS_*D_], g_alq[BS_*D_];
__device__ __nv_bfloat16 g_ahk[BS_*D_], g_alk[BS_*D_];
__device__ __nv_bfloat16 g_ahv[BS_*D_], g_alv[BS_*D_];
__device__ __nv_bfloat16 g_whq[D_*D_], g_wlq[D_*D_];
__device__ __nv_bfloat16 g_whk[D_*D_], g_wlk[D_*D_];
__device__ __nv_bfloat16 g_whv[D_*D_], g_wlv[D_*D_];
__device__ __nv_bfloat16 g_who[D_*D_], g_wlo[D_*D_];
__device__ __nv_bfloat16 g_qh[BH_*S_*DK_], g_ql[BH_*S_*DK_];
__device__ __nv_bfloat16 g_kh[BH_*S_*DK_], g_kl[BH_*S_*DK_];
__device__ __nv_bfloat16 g_vh[BH_*S_*DK_], g_vl[BH_*S_*DK_];

// Batch parameter structs (passed by value)
struct PrepBatch {
    // z = 0..3: weight LoRA+transpose+split
    const float* w[4]; const float* la[4]; const float* lb[4];
    __nv_bfloat16* whi[4]; __nv_bfloat16* wlo[4];
    // z = 4..6: activation split
    const float* x[3];
    __nv_bfloat16* hi[3]; __nv_bfloat16* lo[3];
};
struct GemmBatch {
    const __nv_bfloat16* ah[3]; const __nv_bfloat16* al[3];
    const __nv_bfloat16* wh[3]; const __nv_bfloat16* wl[3];
    const float* bias[3];
    float scale[3];
    float* c[3];
    __nv_bfloat16* chi[3]; __nv_bfloat16* clo[3];
};

// ---------------------------------------------------------------------------
// Combined prep: weight splits (z<4) + activation splits (z>=4), one launch.
// Grid (64, 64, 7), 256 threads. la tile staged through smem (one coalesced
// load per thread) to kill the per-thread L1 gather storm.
// ---------------------------------------------------------------------------
__global__ void prep_kernel(PrepBatch pb)
{
    __shared__ float t[32][33];
    __shared__ float sla[32][8];
    const int z = blockIdx.z;
    if (z < 4) {
        const float* __restrict__ w  = pb.w[z];
        const float* __restrict__ la = pb.la[z];
        const float* __restrict__ lb = pb.lb[z];
        __nv_bfloat16* __restrict__ whi = pb.whi[z];
        __nv_bfloat16* __restrict__ wlo = pb.wlo[z];

        const int k0 = blockIdx.y * 32, n0 = blockIdx.x * 32;
        const int x = threadIdx.x & 31, y = threadIdx.x >> 5;

        // Stage la[k0..k0+32][0..8) into smem: 256 floats, 1 per thread
        sla[threadIdx.x >> 3][threadIdx.x & 7] =
            la[(k0 + (threadIdx.x >> 3)) * 8 + (threadIdx.x & 7)];
        __syncthreads();

#pragma unroll
        for (int i = 0; i < 4; i++) {
            int kl = y + 8 * i;
            float v = w[(k0 + kl) * D_ + n0 + x];
#pragma unroll
            for (int r = 0; r < 8; r++)
                v += sla[kl][r] * lb[r * D_ + n0 + x];
            t[kl][x] = v;
        }
        __syncthreads();
#pragma unroll
        for (int i = 0; i < 4; i++) {
            int nl = y + 8 * i;
            float v = t[x][nl];
            __nv_bfloat16 h = __float2bfloat16(v);
            whi[(n0 + nl) * D_ + k0 + x] = h;
            wlo[(n0 + nl) * D_ + k0 + x] = __float2bfloat16(v - __bfloat162float(h));
        }
    } else {
        const int a = z - 4;
        const float* __restrict__ x = pb.x[a];
        __nv_bfloat16* __restrict__ hi = pb.hi[a];
        __nv_bfloat16* __restrict__ lo = pb.lo[a];

        // linear block over (64,64): 2048 floats per block, 8 per thread
        const int blk = blockIdx.y * 64 + blockIdx.x;
        int i = blk * 2048 + threadIdx.x * 8;
#pragma unroll
        for (int u = 0; u < 2; u++, i += 4) {
            float4 v = *(const float4*)(x + i);
            __nv_bfloat16 h0 = __float2bfloat16(v.x);
            __nv_bfloat16 h1 = __float2bfloat16(v.y);
            __nv_bfloat16 h2 = __float2bfloat16(v.z);
            __nv_bfloat16 h3 = __float2bfloat16(v.w);
            *(__nv_bfloat162*)(hi + i)     = __nv_bfloat162(h0, h1);
            *(__nv_bfloat162*)(hi + i + 2) = __nv_bfloat162(h2, h3);
            *(__nv_bfloat162*)(lo + i) = __nv_bfloat162(
                __float2bfloat16(v.x - __bfloat162float(h0)),
                __float2bfloat16(v.y - __bfloat162float(h1)));
            *(__nv_bfloat162*)(lo + i + 2) = __nv_bfloat162(
                __float2bfloat16(v.z - __bfloat162float(h2)),
                __float2bfloat16(v.w - __bfloat162float(h3)));
        }
    }
}

// ---------------------------------------------------------------------------
// bf16x3 GEMM via mma.sync (R8/R12 config: CTA 128x128, K-chunk 32,
// 2 CTAs/SM). blockIdx.z selects the batch entry. epi==1: bf16 hi/lo
// head-major scaled by gb.scale[z]; epi==0: fp32 row-major.
// ---------------------------------------------------------------------------
#define RSTRIDE 80                        // 64 B data + 16 B pad
#define GT      (128 * RSTRIDE)           // 10240
#define GBUF    (4 * GT)                  // 40960
#define GSMEM   (2 * GBUF)                // 81920 (2 CTAs/SM)

__global__ __launch_bounds__(256, 2) void gemm_bf16x3(GemmBatch gb, int epi)
{
    extern __shared__ char dsm[];
    const uint32_t sb = smem_u32(dsm);

    const int z    = blockIdx.z;
    const int tid  = threadIdx.x;
    const int wid  = tid >> 5;
    const int lane = tid & 31;
    const int wm   = wid >> 1;
    const int wn   = wid & 1;
    const int bm   = blockIdx.y << 7;
    const int bn   = blockIdx.x << 7;

    const __nv_bfloat16* srcs[4] = {
        gb.ah[z] + (size_t)bm * D_, gb.al[z] + (size_t)bm * D_,
        gb.wh[z] + (size_t)bn * D_, gb.wl[z] + (size_t)bn * D_ };
    const float* __restrict__ bias = gb.bias[z];

    float acc[2][8][4];
#pragma unroll
    for (int i = 0; i < 2; i++)
#pragma unroll
        for (int j = 0; j < 8; j++)
#pragma unroll
            for (int q = 0; q < 4; q++) acc[i][j][q] = 0.f;

    const int a_row  = lane & 15;
    const int a_half = lane >> 4;
    const int b_row  = (lane & 7) + ((lane & 16) ? 8 : 0);
    const int b_kh   = (lane >> 3) & 1;

    auto issue_tile = [&](int c, int buf) {
        const uint32_t bb = sb + buf * GBUF;
        const int ke = c * 32;
#pragma unroll
        for (int t = 0; t < 4; t++) {
            const __nv_bfloat16* src = srcs[t] + ke;
            const uint32_t db = bb + t * GT;
#pragma unroll
            for (int j = 0; j < 2; j++) {
                int idx = j * 256 + tid;
                int row = idx >> 2, c16 = idx & 3;
                CP16(db + row * RSTRIDE + c16 * 16,
                     src + (size_t)row * D_ + c16 * 8);
            }
        }
        CP_COMMIT();
    };

    issue_tile(0, 0);

#pragma unroll 1
    for (int c = 0; c < 64; c++) {
        const int buf = c & 1;
        if (c < 63) issue_tile(c + 1, buf ^ 1);
        if (c < 63) { CP_WAIT(1); } else { CP_WAIT(0); }
        __syncthreads();

        const uint32_t bb = sb + buf * GBUF;
        const uint32_t aBase = bb + (wm * 32 + a_row) * RSTRIDE + a_half * 16;
        const uint32_t bBase = bb + 2 * GT + (wn * 64 + b_row) * RSTRIDE + b_kh * 16;

#pragma unroll
        for (int ks = 0; ks < 2; ks++) {
            const uint32_t ko = ks * 32;
            uint32_t ah2[2][4], al2[2][4];
#pragma unroll
            for (int mf = 0; mf < 2; mf++) {
                ldsm4(ah2[mf], aBase + mf * 16 * RSTRIDE + ko);
                ldsm4(al2[mf], aBase + GT + mf * 16 * RSTRIDE + ko);
            }
            uint32_t bh2[4][4], bl2[4][4];
#pragma unroll
            for (int ng = 0; ng < 4; ng++) {
                ldsm4(bh2[ng], bBase + ng * 16 * RSTRIDE + ko);
                ldsm4(bl2[ng], bBase + GT + ng * 16 * RSTRIDE + ko);
            }
#pragma unroll
            for (int mf = 0; mf < 2; mf++) {
#pragma unroll
                for (int ng = 0; ng < 4; ng++) {
                    mma_bf16(acc[mf][2 * ng],     ah2[mf], &bh2[ng][0]);
                    mma_bf16(acc[mf][2 * ng + 1], ah2[mf], &bh2[ng][2]);
                    mma_bf16(acc[mf][2 * ng],     ah2[mf], &bl2[ng][0]);
                    mma_bf16(acc[mf][2 * ng + 1], ah2[mf], &bl2[ng][2]);
                    mma_bf16(acc[mf][2 * ng],     al2[mf], &bh2[ng][0]);
                    mma_bf16(acc[mf][2 * ng + 1], al2[mf], &bh2[ng][2]);
                }
            }
        }
        __syncthreads();
    }

    const int h = blockIdx.x;             // N-tile == one head when epi==1
    const float osc = gb.scale[z];
#pragma unroll
    for (int mf = 0; mf < 2; mf++) {
        const int r0 = bm + wm * 32 + mf * 16 + (lane >> 2);
#pragma unroll
        for (int rr = 0; rr < 2; rr++) {
            const int g = r0 + rr * 8;
            if (epi == 1) {
                int b = g >> 11, s = g & (S_ - 1);
                size_t base = ((size_t)((b * H_ + h) * S_ + s)) * DK_;
                __nv_bfloat16* Chi = gb.chi[z];
                __nv_bfloat16* Clo = gb.clo[z];
#pragma unroll
                for (int nf = 0; nf < 8; nf++) {
                    const int col = wn * 64 + nf * 8 + 2 * (lane & 3);
                    float vx = (acc[mf][nf][2 * rr + 0] + bias[bn + col]) * osc;
                    float vy = (acc[mf][nf][2 * rr + 1] + bias[bn + col + 1]) * osc;
                    __nv_bfloat16 hx = __float2bfloat16(vx);
                    __nv_bfloat16 hy = __float2bfloat16(vy);
                    *(__nv_bfloat162*)(Chi + base + col) = __nv_bfloat162(hx, hy);
                    *(__nv_bfloat162*)(Clo + base + col) = __nv_bfloat162(
                        __float2bfloat16(vx - __bfloat162float(hx)),
                        __float2bfloat16(vy - __bfloat162float(hy)));
                }
            } else {
                float* dst = gb.c[z] + (size_t)g * D_ + bn;
#pragma unroll
                for (int nf = 0; nf < 8; nf++) {
                    const int col = wn * 64 + nf * 8 + 2 * (lane & 3);
                    float2 v;
                    v.x = acc[mf][nf][2 * rr + 0] + bias[bn + col];
                    v.y = acc[mf][nf][2 * rr + 1] + bias[bn + col + 1];
                    *(float2*)(dst + col) = v;
                }
            }
        }
    }
}

// ---------------------------------------------------------------------------
// Tensor-core causal flash attention, bf16x3 splits, fp32 softmax.
// R10 geometry: BM=128 (8 warps x 16 rows), BN=64, dk=128, FR=272.
// Q is pre-scaled by 1/sqrt(dk) in the projection epilogue.
// ---------------------------------------------------------------------------
#define FR       272
#define FQT      (128 * FR)               // 34816
#define FKT      (64 * FR)                // 17408
#define FST      (4 * FKT)                // 69632
#define FST_OFF  (2 * FQT)
#define FSMEM    (2 * FQT + 2 * FST)      // 208896

__global__ __launch_bounds__(256, 1) void flash_tc(
    const __nv_bfloat16* __restrict__ Qh, const __nv_bfloat16* __restrict__ Ql,
    const __nv_bfloat16* __restrict__ Kh, const __nv_bfloat16* __restrict__ Kl,
    const __nv_bfloat16* __restrict__ Vh, const __nv_bfloat16* __restrict__ Vl,
    __nv_bfloat16* __restrict__ Oh, __nv_bfloat16* __restrict__ Ol)
{
    extern __shared__ char dsm[];
    const uint32_t sb = smem_u32(dsm);

    const int tid  = threadIdx.x;
    const int w    = tid >> 5;
    const int lane = tid & 31;
    const int qb   = 15 - blockIdx.x;     // heavy blocks first
    const int bh   = blockIdx.y;
    const int qm0  = qb * 128;

    {
        const __nv_bfloat16* qsrc[2] = {
            Qh + ((size_t)bh * S_ + qm0) * DK_,
            Ql + ((size_t)bh * S_ + qm0) * DK_ };
#pragma unroll
        for (int t = 0; t < 2; t++)
#pragma unroll
            for (int j = 0; j < 8; j++) {
                int idx = j * 256 + tid;
                int row = idx >> 4, c16 = idx & 15;
                CP16(sb + t * FQT + row * FR + c16 * 16,
                     qsrc[t] + (size_t)row * DK_ + c16 * 8);
            }
        CP_COMMIT();
    }
    const __nv_bfloat16* ksrc[4] = {
        Kh + (size_t)bh * S_ * DK_, Kl + (size_t)bh * S_ * DK_,
        Vh + (size_t)bh * S_ * DK_, Vl + (size_t)bh * S_ * DK_ };

    auto issue_kv = [&](int kn, int buf) {
        const uint32_t bb = sb + FST_OFF + buf * FST;
        const int ke = kn * 64;
#pragma unroll
        for (int t = 0; t < 4; t++) {
            const __nv_bfloat16* src = ksrc[t] + (size_t)ke * DK_;
            const uint32_t db = bb + t * FKT;
#pragma unroll
            for (int j = 0; j < 4; j++) {
                int idx = j * 256 + tid;
                int row = idx >> 4, c16 = idx & 15;
                CP16(db + row * FR + c16 * 16,
                     src + (size_t)row * DK_ + c16 * 8);
            }
        }
        CP_COMMIT();
    };
    issue_kv(0, 0);

    float oacc[16][4];
#pragma unroll
    for (int i = 0; i < 16; i++)
#pragma unroll
        for (int q = 0; q < 4; q++) oacc[i][q] = 0.f;
    float m_i[2] = {-1e30f, -1e30f};
    float l_i[2] = {0.f, 0.f};

    const int ntiles = 2 * qb + 2;
    const int grp = lane >> 2, tig = lane & 3;

    const int a_row  = lane & 15, a_half = lane >> 4;
    const int b_row  = (lane & 7) + ((lane & 16) ? 8 : 0);
    const int b_kh   = (lane >> 3) & 1;
    const int vt_row = (lane & 7) + 8 * ((lane >> 3) & 1);
    const int vt_nb  = 16 * (lane >> 4);

#pragma unroll 1
    for (int kn = 0; kn < ntiles; kn++) {
        const int buf = kn & 1;
        if (kn + 1 < ntiles) issue_kv(kn + 1, buf ^ 1);
        if (kn + 1 < ntiles) { CP_WAIT(1); } else { CP_WAIT(0); }
        __syncthreads();

        const uint32_t st = sb + FST_OFF + buf * FST;

        // ---- S = Qh·Kh + Qh·Kl + Ql·Kh  (128x64, fp32 acc) ----
        float sacc[8][4];
#pragma unroll
        for (int i = 0; i < 8; i++)
#pragma unroll
            for (int q = 0; q < 4; q++) sacc[i][q] = 0.f;

        const uint32_t qBase = sb + (16 * w + a_row) * FR + a_half * 16;
        const uint32_t kBase = st + b_row * FR + b_kh * 16;

#pragma unroll
        for (int ks = 0; ks < 8; ks++) {
            const uint32_t ko = ks * 32;
            uint32_t qhf[4], qlf[4];
            ldsm4(qhf, qBase + ko);
            ldsm4(qlf, qBase + FQT + ko);
            uint32_t kh2[4][4], kl2[4][4];
#pragma unroll
            for (int ng = 0; ng < 4; ng++) {
                ldsm4(kh2[ng], kBase + ng * 16 * FR + ko);
                ldsm4(kl2[ng], kBase + FKT + ng * 16 * FR + ko);
            }
#pragma unroll
            for (int ng = 0; ng < 4; ng++) {
                mma_bf16(sacc[2 * ng],     qhf, &kh2[ng][0]);
                mma_bf16(sacc[2 * ng + 1], qhf, &kh2[ng][2]);
                mma_bf16(sacc[2 * ng],     qhf, &kl2[ng][0]);
                mma_bf16(sacc[2 * ng + 1], qhf, &kl2[ng][2]);
                mma_bf16(sacc[2 * ng],     qlf, &kh2[ng][0]);
                mma_bf16(sacc[2 * ng + 1], qlf, &kh2[ng][2]);
            }
        }

        // ---- causal mask (scale pre-folded into Q) ----
        const bool boundary = (kn >= 2 * qb);
        if (boundary) {
            const int r0 = qm0 + 16 * w + grp;
            const int r1 = r0 + 8;
#pragma unroll
            for (int nf = 0; nf < 8; nf++) {
                const int c0 = kn * 64 + nf * 8 + 2 * tig;
                if (c0     > r0) sacc[nf][0] = -1e30f;
                if (c0 + 1 > r0) sacc[nf][1] = -1e30f;
                if (c0     > r1) sacc[nf][2] = -1e30f;
                if (c0 + 1 > r1) sacc[nf][3] = -1e30f;
            }
        }

        // ---- online softmax (per row-half; stats across 4 lanes) ----
#pragma unroll
        for (int hh = 0; hh < 2; hh++) {
            float mx = -1e30f;
#pragma unroll
            for (int nf = 0; nf < 8; nf++)
                mx = fmaxf(mx, fmaxf(sacc[nf][2 * hh], sacc[nf][2 * hh + 1]));
            mx = fmaxf(mx, __shfl_xor_sync(0xffffffffu, mx, 1));
            mx = fmaxf(mx, __shfl_xor_sync(0xffffffffu, mx, 2));
            float mn = fmaxf(m_i[hh], mx);
            float alpha = __expf(m_i[hh] - mn);
            float rs = 0.f;
#pragma unroll
            for (int nf = 0; nf < 8; nf++) {
                float p0 = __expf(sacc[nf][2 * hh]     - mn);
                float p1 = __expf(sacc[nf][2 * hh + 1] - mn);
                sacc[nf][2 * hh] = p0; sacc[nf][2 * hh + 1] = p1;
                rs += p0 + p1;
            }
            rs += __shfl_xor_sync(0xffffffffu, rs, 1);
            rs += __shfl_xor_sync(0xffffffffu, rs, 2);
            l_i[hh] = l_i[hh] * alpha + rs;
            m_i[hh] = mn;
#pragma unroll
            for (int nf = 0; nf < 16; nf++) {
                oacc[nf][2 * hh] *= alpha; oacc[nf][2 * hh + 1] *= alpha;
            }
        }

        // ---- pack P (C-layout -> A-frag), split hi/lo ----
        uint32_t ph[4][4], pl[4][4];
#pragma unroll
        for (int j = 0; j < 4; j++) {
#pragma unroll
            for (int q = 0; q < 4; q++) {
                float x0 = sacc[2 * j + (q >> 1)][(q & 1) ? 2 : 0];
                float x1 = sacc[2 * j + (q >> 1)][(q & 1) ? 3 : 1];
                __nv_bfloat16 h0 = __float2bfloat16(x0);
                __nv_bfloat16 h1 = __float2bfloat16(x1);
                __nv_bfloat162 hp = __nv_bfloat162(h0, h1);
                ph[j][q] = *(uint32_t*)&hp;
                __nv_bfloat162 lp = __nv_bfloat162(
                    __float2bfloat16(x0 - __bfloat162float(h0)),
                    __float2bfloat16(x1 - __bfloat162float(h1)));
                pl[j][q] = *(uint32_t*)&lp;
            }
        }

        // ---- O += Ph·Vh + Ph·Vl + Pl·Vh  (V via ldmatrix.trans) ----
        const uint32_t vBase = st + 2 * FKT + vt_row * FR + vt_nb;
#pragma unroll
        for (int ks = 0; ks < 4; ks++) {
            const uint32_t kro = ks * 16 * FR;
            uint32_t vh2[8][4], vl2[8][4];
#pragma unroll
            for (int vg = 0; vg < 8; vg++) {
                ldsm4t(vh2[vg], vBase + kro + vg * 32);
                ldsm4t(vl2[vg], vBase + FKT + kro + vg * 32);
            }
#pragma unroll
            for (int vg = 0; vg < 8; vg++) {
                mma_bf16(oacc[2 * vg],     ph[ks], &vh2[vg][0]);
                mma_bf16(oacc[2 * vg + 1], ph[ks], &vh2[vg][2]);
                mma_bf16(oacc[2 * vg],     ph[ks], &vl2[vg][0]);
                mma_bf16(oacc[2 * vg + 1], ph[ks], &vl2[vg][2]);
                mma_bf16(oacc[2 * vg],     pl[ks], &vh2[vg][0]);
                mma_bf16(oacc[2 * vg + 1], pl[ks], &vh2[vg][2]);
            }
        }
        __syncthreads();
    }

    // ---- epilogue: normalize, split hi/lo, store token-major [B,S,D] ----
    const int b = bh >> 4, h = bh & 15;
    const float inv0 = 1.f / l_i[0], inv1 = 1.f / l_i[1];
    const int row0 = qm0 + 16 * w + grp;
    const size_t t0 = ((size_t)b * S_ + row0) * D_;
    const size_t t1 = t0 + 8 * D_;
#pragma unroll
    for (int nf = 0; nf < 16; nf++) {
        const int col = h * DK_ + nf * 8 + 2 * tig;
        float v0 = oacc[nf][0] * inv0, v1 = oacc[nf][1] * inv0;
        float v2 = oacc[nf][2] * inv1, v3 = oacc[nf][3] * inv1;
        __nv_bfloat16 h0 = __float2bfloat16(v0), h1 = __float2bfloat16(v1);
        __nv_bfloat16 h2 = __float2bfloat16(v2), h3 = __float2bfloat16(v3);
        *(__nv_bfloat162*)(Oh + t0 + col) = __nv_bfloat162(h0, h1);
        *(__nv_bfloat162*)(Oh + t1 + col) = __nv_bfloat162(h2, h3);
        *(__nv_bfloat162*)(Ol + t0 + col) = __nv_bfloat162(
            __float2bfloat16(v0 - __bfloat162float(h0)),
            __float2bfloat16(v1 - __bfloat162float(h1)));
        *(__nv_bfloat162*)(Ol + t1 + col) = __nv_bfloat162(
            __float2bfloat16(v2 - __bfloat162float(h2)),
            __float2bfloat16(v3 - __bfloat162float(h3)));
    }
}

// ---------------------------------------------------------------------------
// Launcher: 4 launches total.
// ---------------------------------------------------------------------------
extern "C" void kernel_launch(void* const* d_in, const int* in_sizes, int n_in,
                              void* d_out, int out_size)
{
    const float* query = (const float*)d_in[0];
    const float* key   = (const float*)d_in[1];
    const float* value = (const float*)d_in[2];
    const float* wq  = (const float*)d_in[3];
    const float* bq  = (const float*)d_in[4];
    const float* laq = (const float*)d_in[5];
    const float* lbq = (const float*)d_in[6];
    const float* wk  = (const float*)d_in[7];
    const float* bk  = (const float*)d_in[8];
    const float* lak = (const float*)d_in[9];
    const float* lbk = (const float*)d_in[10];
    const float* wv  = (const float*)d_in[11];
    const float* bv  = (const float*)d_in[12];
    const float* lav = (const float*)d_in[13];
    const float* lbv = (const float*)d_in[14];
    const float* wo  = (const float*)d_in[15];
    const float* bo  = (const float*)d_in[16];
    const float* lao = (const float*)d_in[17];
    const float* lbo = (const float*)d_in[18];

    __nv_bfloat16 *ah, *al, *ahq, *alq, *ahk, *alk, *ahv, *alv;
    __nv_bfloat16 *whq, *wlq, *whk, *wlk, *whv, *wlv, *who, *wlo_;
    __nv_bfloat16 *qh, *ql, *kh, *kl, *vh, *vl;
    cudaGetSymbolAddress((void**)&ah,  g_ah);
    cudaGetSymbolAddress((void**)&al,  g_al);
    cudaGetSymbolAddress((void**)&ahq, g_ahq);
    cudaGetSymbolAddress((void**)&alq, g_alq);
    cudaGetSymbolAddress((void**)&ahk, g_ahk);
    cudaGetSymbolAddress((void**)&alk, g_alk);
    cudaGetSymbolAddress((void**)&ahv, g_ahv);
    cudaGetSymbolAddress((void**)&alv, g_alv);
    cudaGetSymbolAddress((void**)&whq, g_whq);
    cudaGetSymbolAddress((void**)&wlq, g_wlq);
    cudaGetSymbolAddress((void**)&whk, g_whk);
    cudaGetSymbolAddress((void**)&wlk, g_wlk);
    cudaGetSymbolAddress((void**)&whv, g_whv);
    cudaGetSymbolAddress((void**)&wlv, g_wlv);
    cudaGetSymbolAddress((void**)&who, g_who);
    cudaGetSymbolAddress((void**)&wlo_, g_wlo);
    cudaGetSymbolAddress((void**)&qh, g_qh);
    cudaGetSymbolAddress((void**)&ql, g_ql);
    cudaGetSymbolAddress((void**)&kh, g_kh);
    cudaGetSymbolAddress((void**)&kl, g_kl);
    cudaGetSymbolAddress((void**)&vh, g_vh);
    cudaGetSymbolAddress((void**)&vl, g_vl);

    cudaFuncSetAttribute((const void*)gemm_bf16x3,
                         cudaFuncAttributeMaxDynamicSharedMemorySize, GSMEM);
    cudaFuncSetAttribute((const void*)flash_tc,
                         cudaFuncAttributeMaxDynamicSharedMemorySize, FSMEM);

    // 1) All weight + activation splits in ONE launch
    PrepBatch pb;
    pb.w[0] = wq; pb.la[0] = laq; pb.lb[0] = lbq; pb.whi[0] = whq; pb.wlo[0] = wlq;
    pb.w[1] = wk; pb.la[1] = lak; pb.lb[1] = lbk; pb.whi[1] = whk; pb.wlo[1] = wlk;
    pb.w[2] = wv; pb.la[2] = lav; pb.lb[2] = lbv; pb.whi[2] = whv; pb.wlo[2] = wlv;
    pb.w[3] = wo; pb.la[3] = lao; pb.lb[3] = lbo; pb.whi[3] = who; pb.wlo[3] = wlo_;
    pb.x[0] = query; pb.hi[0] = ahq; pb.lo[0] = alq;
    pb.x[1] = key;   pb.hi[1] = ahk; pb.lo[1] = alk;
    pb.x[2] = value; pb.hi[2] = ahv; pb.lo[2] = alv;
    prep_kernel<<<dim3(64, 64, 7), 256>>>(pb);

    // 2) Q,K,V projections in ONE launch (Q pre-scaled by 1/sqrt(dk)),
    //    2 CTAs/SM (R12 config — verified fastest).
    const float qscale = 0.08838834764831845f;
    GemmBatch gqkv = {};
    gqkv.ah[0] = ahq; gqkv.al[0] = alq; gqkv.wh[0] = whq; gqkv.wl[0] = wlq;
    gqkv.bias[0] = bq; gqkv.scale[0] = qscale; gqkv.chi[0] = qh; gqkv.clo[0] = ql;
    gqkv.ah[1] = ahk; gqkv.al[1] = alk; gqkv.wh[1] = whk; gqkv.wl[1] = wlk;
    gqkv.bias[1] = bk; gqkv.scale[1] = 1.f; gqkv.chi[1] = kh; gqkv.clo[1] = kl;
    gqkv.ah[2] = ahv; gqkv.al[2] = alv; gqkv.wh[2] = whv; gqkv.wl[2] = wlv;
    gqkv.bias[2] = bv; gqkv.scale[2] = 1.f; gqkv.chi[2] = vh; gqkv.clo[2] = vl;
    gemm_bf16x3<<<dim3(D_ / 128, BS_ / 128, 3), 256, GSMEM>>>(gqkv, 1);

    // 3) Tensor-core causal flash attention (R10 geometry)
    flash_tc<<<dim3(16, BH_), 256, FSMEM>>>(qh, ql, kh, kl, vh, vl, ah, al);

    // 4) Output projection -> d_out (fp32), 2 CTAs/SM
    GemmBatch go = {};
    go.ah[0] = ah; go.al[0] = al; go.wh[0] = who; go.wl[0] = wlo_;
    go.bias[0] = bo; go.scale[0] = 1.f; go.c[0] = (float*)d_out;
    gemm_bf16x3<<<dim3(D_ / 128, BS_ / 128, 1), 256, GSMEM>>>(go, 0);
}